// round 2
// baseline (speedup 1.0000x reference)
#include <cuda_runtime.h>
#include <cuda_bf16.h>

// Shapes (fixed by the problem)
#define B_   16
#define T_   24
#define N_   512
#define D_   128
#define K3_  384          // 3*D
#define Z_   12
#define ROWS_PER_BLK 32   // rows (b,n pairs) per block
#define KC   32           // K-chunk for W1 staging
#define XPAD 388          // 384 + 4 (multiple of 4 for float4 alignment)
#define WPAD 132          // 128 + 4

#define NEG_SLOPE 0.01f

// smem layout (floats):
//   Xs  [ROWS_PER_BLK][XPAD]   input rows (concat of 3 slices), row-major
//   Ws  [KC][WPAD]             transposed W1 chunk; reused as Ys[32][WPAD] for GEMM2
#define XS_FLOATS (ROWS_PER_BLK * XPAD)
#define WS_FLOATS (KC * WPAD)
#define SMEM_BYTES ((XS_FLOATS + WS_FLOATS) * 4)

__global__ void __launch_bounds__(256, 3)
fusion_kernel(const float* __restrict__ Ht,
              const float* __restrict__ Hs,
              const float* __restrict__ Hm,
              const float* __restrict__ W1,   // [128][384] row-major
              const float* __restrict__ b1,   // [128]
              const float* __restrict__ W2,   // [12][128] row-major
              const float* __restrict__ b2,   // [12]
              float* __restrict__ out)        // [16][12][512]
{
    extern __shared__ float sm[];
    float* Xs = sm;                 // [32][XPAD]
    float* Ws = sm + XS_FLOATS;     // [KC][WPAD] (later Ys[32][WPAD])

    const int tid = threadIdx.x;
    const int rowBase = blockIdx.x * ROWS_PER_BLK;   // global row = b*512 + n

    // ---- load X tile: 32 rows x 96 float4 (3 segments of 32 float4) ----
    {
        const float* segs[3] = {Ht, Hs, Hm};
        #pragma unroll
        for (int it = 0; it < 12; ++it) {
            int idx = it * 256 + tid;            // 0..3071
            int r   = idx / 96;
            int f   = idx - r * 96;
            int seg = f >> 5;                    // 0..2
            int d4  = f & 31;                    // 0..31
            int grow = rowBase + r;
            int b = grow >> 9;
            int n = grow & 511;
            // last timestep t = T_-1
            const float* src = segs[seg] + (((size_t)b * T_ + (T_ - 1)) * N_ + n) * D_ + d4 * 4;
            float4 v = *reinterpret_cast<const float4*>(src);
            *reinterpret_cast<float4*>(&Xs[r * XPAD + seg * D_ + d4 * 4]) = v;
        }
    }

    // ---- GEMM1: acc[4][4] per thread; thread (ty,tx): rows ty*4.., cols tx*4.. ----
    const int ty = tid >> 5;     // 0..7  -> 4 rows each = 32 rows
    const int tx = tid & 31;     // 0..31 -> 4 cols each = 128 cols

    float acc[4][4];
    #pragma unroll
    for (int i = 0; i < 4; ++i)
        #pragma unroll
        for (int j = 0; j < 4; ++j) acc[i][j] = 0.f;

    for (int cb = 0; cb < K3_; cb += KC) {
        __syncthreads();
        // load W1 chunk transposed: Ws[k][d] = W1[d][cb+k]
        // 128 d * 8 float4 = 1024 float4 -> 4 per thread
        #pragma unroll
        for (int it = 0; it < 4; ++it) {
            int idx = it * 256 + tid;       // 0..1023
            int d  = idx >> 3;              // 0..127
            int f4 = idx & 7;               // 0..7
            int k0 = f4 * 4;
            float4 w = *reinterpret_cast<const float4*>(W1 + (size_t)d * K3_ + cb + k0);
            Ws[(k0 + 0) * WPAD + d] = w.x;
            Ws[(k0 + 1) * WPAD + d] = w.y;
            Ws[(k0 + 2) * WPAD + d] = w.z;
            Ws[(k0 + 3) * WPAD + d] = w.w;
        }
        __syncthreads();

        #pragma unroll 8
        for (int k = 0; k < KC; ++k) {
            float4 w = *reinterpret_cast<const float4*>(&Ws[k * WPAD + tx * 4]);
            float x0 = Xs[(ty * 4 + 0) * XPAD + cb + k];
            float x1 = Xs[(ty * 4 + 1) * XPAD + cb + k];
            float x2 = Xs[(ty * 4 + 2) * XPAD + cb + k];
            float x3 = Xs[(ty * 4 + 3) * XPAD + cb + k];
            acc[0][0] += x0 * w.x; acc[0][1] += x0 * w.y; acc[0][2] += x0 * w.z; acc[0][3] += x0 * w.w;
            acc[1][0] += x1 * w.x; acc[1][1] += x1 * w.y; acc[1][2] += x1 * w.z; acc[1][3] += x1 * w.w;
            acc[2][0] += x2 * w.x; acc[2][1] += x2 * w.y; acc[2][2] += x2 * w.z; acc[2][3] += x2 * w.w;
            acc[3][0] += x3 * w.x; acc[3][1] += x3 * w.y; acc[3][2] += x3 * w.z; acc[3][3] += x3 * w.w;
        }
    }

    // ---- bias + LeakyReLU, write activated tile to Ys (= Ws region) ----
    __syncthreads();   // all done reading Ws chunk
    float* Ys = Ws;    // [32][WPAD]
    #pragma unroll
    for (int i = 0; i < 4; ++i) {
        float4 v;
        float* a = acc[i];
        #pragma unroll
        for (int j = 0; j < 4; ++j) {
            float bv = __ldg(b1 + tx * 4 + j);
            float y  = a[j] + bv;
            a[j] = (y > 0.f) ? y : NEG_SLOPE * y;
        }
        v.x = a[0]; v.y = a[1]; v.z = a[2]; v.w = a[3];
        *reinterpret_cast<float4*>(&Ys[(ty * 4 + i) * WPAD + tx * 4]) = v;
    }
    __syncthreads();

    // ---- GEMM2: 32 rows x 12 z = 384 outputs ----
    #pragma unroll
    for (int it = 0; it < 2; ++it) {
        int o = it * 256 + tid;
        if (o < ROWS_PER_BLK * Z_) {
            int r = o / Z_;
            int z = o - r * Z_;
            float s = __ldg(b2 + z);
            const float* w2 = W2 + z * D_;
            const float* yr = &Ys[r * WPAD];
            #pragma unroll 16
            for (int d = 0; d < D_; ++d)
                s += yr[d] * __ldg(w2 + d);
            int grow = rowBase + r;
            int b = grow >> 9;
            int n = grow & 511;
            out[((size_t)b * Z_ + z) * N_ + n] = s;
        }
    }
}

extern "C" void kernel_launch(void* const* d_in, const int* in_sizes, int n_in,
                              void* d_out, int out_size)
{
    const float* Ht = (const float*)d_in[0];
    const float* Hs = (const float*)d_in[1];
    const float* Hm = (const float*)d_in[2];
    const float* W1 = (const float*)d_in[3];
    const float* b1 = (const float*)d_in[4];
    const float* W2 = (const float*)d_in[5];
    const float* b2 = (const float*)d_in[6];
    float* out = (float*)d_out;

    cudaFuncSetAttribute(fusion_kernel,
                         cudaFuncAttributeMaxDynamicSharedMemorySize, SMEM_BYTES);

    int grid = (B_ * N_) / ROWS_PER_BLK;   // 256 blocks
    fusion_kernel<<<grid, 256, SMEM_BYTES>>>(Ht, Hs, Hm, W1, b1, W2, b2, out);
}

// round 4
// speedup vs baseline: 2.0592x; 2.0592x over previous
#include <cuda_runtime.h>
#include <cuda_bf16.h>
#include <cstdint>

// Problem shapes
#define B_ 16
#define T_ 24
#define N_ 512
#define D_ 128
#define Z_ 12
#define NEG_SLOPE 0.01f

#define MROWS 64           // rows per CTA
#define NCHUNK 3           // K chunks of 128 (= one source segment each)

// smem: bf16 tiles with 272-byte padded rows (128 bf16 = 256B + 16B pad
// -> consecutive rows shift by 4 banks -> conflict-free fragment loads)
#define ASTRIDE 272
#define OFF_AH  0
#define OFF_AL  (64 * ASTRIDE)
#define OFF_BH  (2 * 64 * ASTRIDE)
#define OFF_BL  (2 * 64 * ASTRIDE + 128 * ASTRIDE)
#define SMEM_BYTES (2 * 64 * ASTRIDE + 2 * 128 * ASTRIDE)   // 104448
#define YSTRIDE 132        // floats; Ys[64][132] reuses the A region (33792B <= 34816B)

// pack two floats to bf16x2 (round-to-nearest), returning residuals
__device__ __forceinline__ uint32_t pack_hi(float a, float b, float& ra, float& rb) {
    __nv_bfloat16 ha = __float2bfloat16(a), hb = __float2bfloat16(b);
    ra = a - __bfloat162float(ha);
    rb = b - __bfloat162float(hb);
    __nv_bfloat162 p; p.x = ha; p.y = hb;
    return *reinterpret_cast<uint32_t*>(&p);
}
__device__ __forceinline__ uint32_t pack_lo(float a, float b) {
    __nv_bfloat16 ha = __float2bfloat16(a), hb = __float2bfloat16(b);
    __nv_bfloat162 p; p.x = ha; p.y = hb;
    return *reinterpret_cast<uint32_t*>(&p);
}

// D += A * B   (m16n8k16, bf16 inputs, fp32 accum)
__device__ __forceinline__ void mma16816(float* c, const uint32_t* a, uint32_t b0, uint32_t b1) {
    asm volatile(
        "mma.sync.aligned.m16n8k16.row.col.f32.bf16.bf16.f32 "
        "{%0,%1,%2,%3},{%4,%5,%6,%7},{%8,%9},{%0,%1,%2,%3};"
        : "+f"(c[0]), "+f"(c[1]), "+f"(c[2]), "+f"(c[3])
        : "r"(a[0]), "r"(a[1]), "r"(a[2]), "r"(a[3]), "r"(b0), "r"(b1));
}

__global__ void __launch_bounds__(256, 1)
fusion_mma_kernel(const float* __restrict__ Ht,
                  const float* __restrict__ Hs,
                  const float* __restrict__ Hm,
                  const float* __restrict__ W1,   // [128][384]
                  const float* __restrict__ b1,   // [128]
                  const float* __restrict__ W2,   // [12][128]
                  const float* __restrict__ b2,   // [12]
                  float* __restrict__ out)        // [16][12][512]
{
    extern __shared__ char smem[];
    const int tid  = threadIdx.x;
    const int wid  = tid >> 5;
    const int lane = tid & 31;
    const int g    = lane >> 2;      // group id 0..7
    const int t    = lane & 3;       // thread-in-group
    const int warpM = wid >> 1;      // 0..3 -> rows warpM*16
    const int warpN = wid & 1;       // 0..1 -> cols warpN*64
    const int rowBase = blockIdx.x * MROWS;

    const float* segs[3] = {Ht, Hs, Hm};

    float acc[8][4];
    #pragma unroll
    for (int j = 0; j < 8; ++j)
        #pragma unroll
        for (int i = 0; i < 4; ++i) acc[j][i] = 0.f;

    // prefetch A chunk 0 into regs: 8 float4/thread (64 rows x 32 float4)
    float4 regA[8];
    #pragma unroll
    for (int i = 0; i < 8; ++i) {
        int idx = i * 256 + tid;
        int r = idx >> 5, f4 = idx & 31;
        int grp = rowBase + r;
        int b = grp >> 9, n = grp & 511;
        regA[i] = *reinterpret_cast<const float4*>(
            segs[0] + (((size_t)b * T_ + (T_ - 1)) * N_ + n) * D_ + f4 * 4);
    }

    #pragma unroll
    for (int c = 0; c < NCHUNK; ++c) {
        // ---- STS A chunk (hi/lo split) from prefetched regs ----
        #pragma unroll
        for (int i = 0; i < 8; ++i) {
            int idx = i * 256 + tid;
            int r = idx >> 5, f4 = idx & 31;
            float4 v = regA[i];
            float r0, r1, r2, r3;
            uint32_t h01 = pack_hi(v.x, v.y, r0, r1);
            uint32_t h23 = pack_hi(v.z, v.w, r2, r3);
            *reinterpret_cast<uint2*>(smem + OFF_AH + r * ASTRIDE + f4 * 8) = make_uint2(h01, h23);
            *reinterpret_cast<uint2*>(smem + OFF_AL + r * ASTRIDE + f4 * 8) =
                make_uint2(pack_lo(r0, r1), pack_lo(r2, r3));
        }
        // ---- load + split + STS B chunk: W1 cols [c*128, c*128+128) ----
        #pragma unroll
        for (int i = 0; i < 16; ++i) {
            int idx = i * 256 + tid;
            int n = idx >> 5, f4 = idx & 31;
            float4 v = *reinterpret_cast<const float4*>(W1 + (size_t)n * 384 + c * 128 + f4 * 4);
            float r0, r1, r2, r3;
            uint32_t h01 = pack_hi(v.x, v.y, r0, r1);
            uint32_t h23 = pack_hi(v.z, v.w, r2, r3);
            *reinterpret_cast<uint2*>(smem + OFF_BH + n * ASTRIDE + f4 * 8) = make_uint2(h01, h23);
            *reinterpret_cast<uint2*>(smem + OFF_BL + n * ASTRIDE + f4 * 8) =
                make_uint2(pack_lo(r0, r1), pack_lo(r2, r3));
        }
        __syncthreads();

        // prefetch next A chunk (overlaps with MMA below)
        if (c < NCHUNK - 1) {
            const float* src = segs[c + 1];
            #pragma unroll
            for (int i = 0; i < 8; ++i) {
                int idx = i * 256 + tid;
                int r = idx >> 5, f4 = idx & 31;
                int grp = rowBase + r;
                int b = grp >> 9, n = grp & 511;
                regA[i] = *reinterpret_cast<const float4*>(
                    src + (((size_t)b * T_ + (T_ - 1)) * N_ + n) * D_ + f4 * 4);
            }
        }

        // ---- MMA: 8 k16-steps, 8 n-tiles, 3 terms ----
        const char* Abase = smem + (warpM * 16 + g) * ASTRIDE + t * 4;
        const char* Bbase = smem + (warpN * 64 + g) * ASTRIDE + t * 4;
        #pragma unroll
        for (int kk = 0; kk < 8; ++kk) {
            uint32_t ah[4], al[4];
            const char* pa = Abase + kk * 32;
            ah[0] = *reinterpret_cast<const uint32_t*>(pa + OFF_AH);
            ah[1] = *reinterpret_cast<const uint32_t*>(pa + OFF_AH + 8 * ASTRIDE);
            ah[2] = *reinterpret_cast<const uint32_t*>(pa + OFF_AH + 16);
            ah[3] = *reinterpret_cast<const uint32_t*>(pa + OFF_AH + 8 * ASTRIDE + 16);
            al[0] = *reinterpret_cast<const uint32_t*>(pa + OFF_AL);
            al[1] = *reinterpret_cast<const uint32_t*>(pa + OFF_AL + 8 * ASTRIDE);
            al[2] = *reinterpret_cast<const uint32_t*>(pa + OFF_AL + 16);
            al[3] = *reinterpret_cast<const uint32_t*>(pa + OFF_AL + 8 * ASTRIDE + 16);
            #pragma unroll
            for (int j = 0; j < 8; ++j) {
                const char* pb = Bbase + j * 8 * ASTRIDE + kk * 32;
                uint32_t bh0 = *reinterpret_cast<const uint32_t*>(pb + OFF_BH);
                uint32_t bh1 = *reinterpret_cast<const uint32_t*>(pb + OFF_BH + 16);
                uint32_t bl0 = *reinterpret_cast<const uint32_t*>(pb + OFF_BL);
                uint32_t bl1 = *reinterpret_cast<const uint32_t*>(pb + OFF_BL + 16);
                mma16816(acc[j], ah, bh0, bh1);   // hi*hi
                mma16816(acc[j], ah, bl0, bl1);   // hi*lo
                mma16816(acc[j], al, bh0, bh1);   // lo*hi
            }
        }
        __syncthreads();
    }

    // ---- epilogue: bias + LeakyReLU -> Ys smem (reuses A region) ----
    float* Ys = reinterpret_cast<float*>(smem);
    #pragma unroll
    for (int j = 0; j < 8; ++j) {
        int col = warpN * 64 + j * 8 + 2 * t;
        float bv0 = __ldg(b1 + col), bv1 = __ldg(b1 + col + 1);
        int row0 = warpM * 16 + g;
        float y0 = acc[j][0] + bv0; y0 = (y0 > 0.f) ? y0 : NEG_SLOPE * y0;
        float y1 = acc[j][1] + bv1; y1 = (y1 > 0.f) ? y1 : NEG_SLOPE * y1;
        float y2 = acc[j][2] + bv0; y2 = (y2 > 0.f) ? y2 : NEG_SLOPE * y2;
        float y3 = acc[j][3] + bv1; y3 = (y3 > 0.f) ? y3 : NEG_SLOPE * y3;
        *reinterpret_cast<float2*>(Ys + row0 * YSTRIDE + col)       = make_float2(y0, y1);
        *reinterpret_cast<float2*>(Ys + (row0 + 8) * YSTRIDE + col) = make_float2(y2, y3);
    }
    __syncthreads();

    // ---- GEMM2: 64 rows x 12 z = 768 outputs, 3 per thread ----
    #pragma unroll
    for (int it = 0; it < 3; ++it) {
        int o = it * 256 + tid;
        int r = o / Z_, z = o - r * Z_;
        float s = __ldg(b2 + z);
        const float4* w = reinterpret_cast<const float4*>(W2 + (size_t)z * D_);
        const float4* y = reinterpret_cast<const float4*>(Ys + r * YSTRIDE);
        #pragma unroll 8
        for (int d4 = 0; d4 < 32; ++d4) {
            float4 wv = __ldg(w + d4);
            float4 yv = y[d4];
            s += yv.x * wv.x + yv.y * wv.y + yv.z * wv.z + yv.w * wv.w;
        }
        int grp = rowBase + r;
        int b = grp >> 9, n = grp & 511;
        out[((size_t)b * Z_ + z) * N_ + n] = s;
    }
}

extern "C" void kernel_launch(void* const* d_in, const int* in_sizes, int n_in,
                              void* d_out, int out_size)
{
    const float* Ht = (const float*)d_in[0];
    const float* Hs = (const float*)d_in[1];
    const float* Hm = (const float*)d_in[2];
    const float* W1 = (const float*)d_in[3];
    const float* b1 = (const float*)d_in[4];
    const float* W2 = (const float*)d_in[5];
    const float* b2 = (const float*)d_in[6];
    float* out = (float*)d_out;

    cudaFuncSetAttribute(fusion_mma_kernel,
                         cudaFuncAttributeMaxDynamicSharedMemorySize, SMEM_BYTES);

    int grid = (B_ * N_) / MROWS;   // 128 CTAs
    fusion_mma_kernel<<<grid, 256, SMEM_BYTES>>>(Ht, Hs, Hm, W1, b1, W2, b2, out);
}